// round 1
// baseline (speedup 1.0000x reference)
#include <cuda_runtime.h>
#include <math.h>

#define BATCH 16
#define CH 512
#define RES 64
#define HW 4096
#define OT 32     // output channels per CTA
#define KC 16     // c-chunk
#define NTHR 512

// scratch (no allocations allowed)
__device__ float g_s[BATCH * CH];      // conv styles
__device__ float g_s2[BATCH * CH];     // rgb styles (incl. weight_gain)
__device__ float g_dcoef[BATCH * CH];  // demod coefficients
__device__ float g_wsq[CH * CH];       // sum_k conv_w[o,c,k]^2

// ---------------- styles: s[b,c] = ws[b,0]@caw[c] + cab[c]; s2 likewise ----------------
__global__ void k_style(const float* __restrict__ ws, const float* __restrict__ caw,
                        const float* __restrict__ cab, const float* __restrict__ raw,
                        const float* __restrict__ rab) {
    int widx = blockIdx.x * 8 + (threadIdx.x >> 5);   // 8192 warps = (b,c) pairs
    int lane = threadIdx.x & 31;
    int b = widx >> 9, c = widx & 511;
    const float* w0 = ws + b * 1024;
    const float* w1 = w0 + 512;
    const float* ca = caw + c * 512;
    const float* ra = raw + c * 512;
    float a1 = 0.f, a2 = 0.f;
    for (int d = lane; d < 512; d += 32) {
        a1 = fmaf(w0[d], ca[d], a1);
        a2 = fmaf(w1[d], ra[d], a2);
    }
    #pragma unroll
    for (int o = 16; o; o >>= 1) {
        a1 += __shfl_xor_sync(0xffffffffu, a1, o);
        a2 += __shfl_xor_sync(0xffffffffu, a2, o);
    }
    if (lane == 0) {
        g_s[b * 512 + c] = a1 + cab[c];
        g_s2[b * 512 + c] = (a2 + rab[c]) * 0.04419417382415922f;  // 1/sqrt(512)
    }
}

// ---------------- wsq[o,c] = sum_k conv_w[o,c,k]^2 ----------------
__global__ void k_wsq(const float* __restrict__ cw) {
    int idx = blockIdx.x * 256 + threadIdx.x;  // o*512+c, exactly 262144
    const float* p = cw + (size_t)idx * 9;
    float s = 0.f;
    #pragma unroll
    for (int k = 0; k < 9; k++) s = fmaf(p[k], p[k], s);
    g_wsq[idx] = s;
}

// ---------------- dcoef[b,o] = rsqrt(sum_c wsq[o,c]*s[b,c]^2 + 1e-8) ----------------
__global__ void k_dcoef() {
    int widx = blockIdx.x * 8 + (threadIdx.x >> 5);  // 8192 warps = (b,o)
    int lane = threadIdx.x & 31;
    int b = widx >> 9, o = widx & 511;
    const float* wq = g_wsq + o * 512;
    const float* sp = g_s + b * 512;
    float a = 0.f;
    for (int c = lane; c < 512; c += 32) {
        float sv = sp[c];
        a = fmaf(wq[c] * sv, sv, a);
    }
    #pragma unroll
    for (int off = 16; off; off >>= 1) a += __shfl_xor_sync(0xffffffffu, a, off);
    if (!lane) g_dcoef[b * 512 + o] = rsqrtf(a + 1e-8f);
}

// ---------------- main fused kernel ----------------
// CTA: one image row y, 32 output channels, ALL 16 batches.
// x[b,o,y,:] = lrelu( dcoef[b,o] * sum_c s[b,c]*z[o,c,y,:] + noise + bias ) * sqrt(2)
__global__ __launch_bounds__(NTHR, 1)
void k_main(const float* __restrict__ cst, const float* __restrict__ cw,
            const float* __restrict__ cb, const float* __restrict__ nzc,
            const float* __restrict__ nzs, float* __restrict__ out) {
    __shared__ float sm_w[KC][OT][12];   // [cc][o][k], pad 9->12 (16B aligned rows)
    __shared__ float sm_c[KC][3][72];    // [cc][row][col+1], zero-padded cols 0 and 65
    __shared__ float sm_s[KC][16];       // [cc][b]

    const int y = blockIdx.x;
    const int obase = blockIdx.y * OT;
    const int tid = threadIdx.x;
    const int ol = tid >> 4;       // 0..31 output channel within tile
    const int pg = tid & 15;       // pixel group
    const int x0 = pg << 2;        // 4 contiguous pixels
    const int og = obase + ol;

    if (tid < KC * 3) {  // zero halo columns once
        sm_c[tid / 3][tid % 3][0] = 0.f;
        sm_c[tid / 3][tid % 3][65] = 0.f;
    }

    float acc[16][4];
    #pragma unroll
    for (int b = 0; b < 16; b++) {
        acc[b][0] = 0.f; acc[b][1] = 0.f; acc[b][2] = 0.f; acc[b][3] = 0.f;
    }

    for (int c0 = 0; c0 < CH; c0 += KC) {
        __syncthreads();
        {   // weights: thread (oo, cc) loads 9 taps
            int cc = tid & 15;
            int oo = tid >> 4;
            const float* gp = cw + ((size_t)(obase + oo) * CH + (c0 + cc)) * 9;
            #pragma unroll
            for (int k = 0; k < 9; k++) sm_w[cc][oo][k] = gp[k];
        }
        // const rows y-1..y+1 for KC channels (3072 elems over 512 threads)
        for (int i = tid; i < KC * 192; i += NTHR) {
            int cc = i / 192;
            int rem = i - cc * 192;
            int r = rem >> 6;
            int col = rem & 63;
            int yy = y + r - 1;
            float v = 0.f;
            if ((unsigned)yy < 64u) v = cst[(size_t)(c0 + cc) * HW + yy * 64 + col];
            sm_c[cc][r][col + 1] = v;
        }
        if (tid < KC * 16) {
            int cc = tid >> 4, b = tid & 15;
            sm_s[cc][b] = g_s[b * CH + c0 + cc];
        }
        __syncthreads();

        #pragma unroll 4
        for (int cc = 0; cc < KC; cc++) {
            float4 w03 = *(const float4*)&sm_w[cc][ol][0];
            float4 w47 = *(const float4*)&sm_w[cc][ol][4];
            float  w8  = sm_w[cc][ol][8];
            float z0, z1, z2, z3;
            {   // row y-1 : taps w0,w1,w2
                float4 a = *(const float4*)&sm_c[cc][0][x0];
                float2 e = *(const float2*)&sm_c[cc][0][x0 + 4];
                z0 = fmaf(w03.x, a.x, fmaf(w03.y, a.y, w03.z * a.z));
                z1 = fmaf(w03.x, a.y, fmaf(w03.y, a.z, w03.z * a.w));
                z2 = fmaf(w03.x, a.z, fmaf(w03.y, a.w, w03.z * e.x));
                z3 = fmaf(w03.x, a.w, fmaf(w03.y, e.x, w03.z * e.y));
            }
            {   // row y : taps w3,w4,w5
                float4 a = *(const float4*)&sm_c[cc][1][x0];
                float2 e = *(const float2*)&sm_c[cc][1][x0 + 4];
                z0 = fmaf(w03.w, a.x, fmaf(w47.x, a.y, fmaf(w47.y, a.z, z0)));
                z1 = fmaf(w03.w, a.y, fmaf(w47.x, a.z, fmaf(w47.y, a.w, z1)));
                z2 = fmaf(w03.w, a.z, fmaf(w47.x, a.w, fmaf(w47.y, e.x, z2)));
                z3 = fmaf(w03.w, a.w, fmaf(w47.x, e.x, fmaf(w47.y, e.y, z3)));
            }
            {   // row y+1 : taps w6,w7,w8
                float4 a = *(const float4*)&sm_c[cc][2][x0];
                float2 e = *(const float2*)&sm_c[cc][2][x0 + 4];
                z0 = fmaf(w47.z, a.x, fmaf(w47.w, a.y, fmaf(w8, a.z, z0)));
                z1 = fmaf(w47.z, a.y, fmaf(w47.w, a.z, fmaf(w8, a.w, z1)));
                z2 = fmaf(w47.z, a.z, fmaf(w47.w, a.w, fmaf(w8, e.x, z2)));
                z3 = fmaf(w47.z, a.w, fmaf(w47.w, e.x, fmaf(w8, e.y, z3)));
            }
            float zz[4] = {z0, z1, z2, z3};
            float sv[16];
            *(float4*)&sv[0]  = *(const float4*)&sm_s[cc][0];
            *(float4*)&sv[4]  = *(const float4*)&sm_s[cc][4];
            *(float4*)&sv[8]  = *(const float4*)&sm_s[cc][8];
            *(float4*)&sv[12] = *(const float4*)&sm_s[cc][12];
            #pragma unroll
            for (int b = 0; b < 16; b++)
                #pragma unroll
                for (int j = 0; j < 4; j++)
                    acc[b][j] = fmaf(sv[b], zz[j], acc[b][j]);
        }
    }

    // epilogue: demod, noise, bias, lrelu*sqrt(2), coalesced float4 stores
    float nsv = nzs[0];
    float nv[4];
    #pragma unroll
    for (int j = 0; j < 4; j++) nv[j] = nzc[y * 64 + x0 + j] * nsv;
    float bo = cb[og];
    const float gain = 1.4142135623730951f;
    size_t pxoff = (size_t)y * 64 + x0;
    #pragma unroll
    for (int b = 0; b < 16; b++) {
        float dc = g_dcoef[b * CH + og];
        float4 v;
        float t;
        t = fmaf(acc[b][0], dc, nv[0] + bo); v.x = (t > 0.f ? t : 0.2f * t) * gain;
        t = fmaf(acc[b][1], dc, nv[1] + bo); v.y = (t > 0.f ? t : 0.2f * t) * gain;
        t = fmaf(acc[b][2], dc, nv[2] + bo); v.z = (t > 0.f ? t : 0.2f * t) * gain;
        t = fmaf(acc[b][3], dc, nv[3] + bo); v.w = (t > 0.f ? t : 0.2f * t) * gain;
        *(float4*)(out + ((size_t)(b * CH + og)) * HW + pxoff) = v;
    }
}

// ---------------- ToRGB: img[b,i,hw] = sum_o rgb_w[i,o]*s2[b,o]*x[b,o,hw] + rgb_b[i] ----------------
__global__ void k_rgb(const float* __restrict__ x, const float* __restrict__ rgbw,
                      const float* __restrict__ rgbb, float* __restrict__ img) {
    __shared__ float rw[3][512];
    int b = blockIdx.y;
    int px = blockIdx.x * 256 + threadIdx.x;
    for (int i = threadIdx.x; i < 1536; i += 256) {
        int ch = i >> 9, o = i & 511;
        rw[ch][o] = rgbw[ch * 512 + o] * g_s2[b * 512 + o];
    }
    __syncthreads();
    const float* xp = x + (size_t)b * CH * HW + px;
    float a0 = 0.f, a1 = 0.f, a2 = 0.f;
    #pragma unroll 8
    for (int o = 0; o < 512; o++) {
        float xv = xp[(size_t)o * HW];
        a0 = fmaf(rw[0][o], xv, a0);
        a1 = fmaf(rw[1][o], xv, a1);
        a2 = fmaf(rw[2][o], xv, a2);
    }
    size_t base = (size_t)b * 3 * HW + px;
    img[base] = a0 + rgbb[0];
    img[base + HW] = a1 + rgbb[1];
    img[base + 2 * HW] = a2 + rgbb[2];
}

extern "C" void kernel_launch(void* const* d_in, const int* in_sizes, int n_in,
                              void* d_out, int out_size) {
    const float* ws   = (const float*)d_in[0];   // [16,2,512]
    const float* cst  = (const float*)d_in[1];   // [512,64,64]
    const float* cw   = (const float*)d_in[2];   // [512,512,3,3]
    const float* cb   = (const float*)d_in[3];   // [512]
    const float* caw  = (const float*)d_in[4];   // [512,512]
    const float* cab  = (const float*)d_in[5];   // [512]
    const float* nzc  = (const float*)d_in[6];   // [64,64]
    const float* nzs  = (const float*)d_in[7];   // [1]
    const float* rgbw = (const float*)d_in[8];   // [3,512,1,1]
    const float* rgbb = (const float*)d_in[9];   // [3]
    const float* raw  = (const float*)d_in[10];  // [512,512]
    const float* rab  = (const float*)d_in[11];  // [512]
    float* out = (float*)d_out;

    k_style<<<1024, 256>>>(ws, caw, cab, raw, rab);
    k_wsq<<<1024, 256>>>(cw);
    k_dcoef<<<1024, 256>>>();
    dim3 g(64, 16);  // 64 rows x 16 o-tiles
    k_main<<<g, NTHR>>>(cst, cw, cb, nzc, nzs, out);
    k_rgb<<<dim3(16, 16), 256>>>(out, rgbw, rgbb, out + (size_t)BATCH * CH * HW);
}